// round 3
// baseline (speedup 1.0000x reference)
#include <cuda_runtime.h>
#include <cstdint>

#define NN 50000
#define NE 800000
constexpr float NEG_SLOPE = 0.2f;

// ---------------- scratch (device globals; no allocation) ----------------
__device__ float g_h  [NN * 256];   // per-layer transformed features
__device__ float g_num[NN * 256];   // aggregation numerator
__device__ float g_z1 [NN * 256];
__device__ float g_z2 [NN * 32];
__device__ float g_r1 [NN * 256];
__device__ float g_als[NN * 8];
__device__ float g_ald[NN * 8];
__device__ float g_den[NN * 8];

// ---------------- vector red helpers (sm_90+) ----------------
__device__ __forceinline__ void red_add4(float4* p, float4 v) {
    asm volatile("red.global.add.v4.f32 [%0], {%1,%2,%3,%4};"
                 :: "l"(p), "f"(v.x), "f"(v.y), "f"(v.z), "f"(v.w) : "memory");
}
__device__ __forceinline__ void red_add1(float* p, float v) {
    asm volatile("red.global.add.f32 [%0], %1;" :: "l"(p), "f"(v) : "memory");
}

// ---------------- SGEMM: C[N,M] = A[N,K] @ B[K,M] ----------------
template <int BM, int BN, int BK, int TM, int TN>
__global__ void __launch_bounds__((BM / TM) * (BN / TN))
sgemm_kernel(int N, int K, int M,
             const float* __restrict__ A, const float* __restrict__ B,
             float* __restrict__ C) {
    constexpr int TX = BN / TN;
    constexpr int TY = BM / TM;
    constexpr int THREADS = TX * TY;

    __shared__ float As[BK][BM];
    __shared__ float Bs[BK][BN];

    const int tid = threadIdx.x;
    const int tx = tid % TX;
    const int ty = tid / TX;
    const int row0 = blockIdx.x * BM;
    const int col0 = blockIdx.y * BN;

    float acc[TM][TN];
#pragma unroll
    for (int m = 0; m < TM; m++)
#pragma unroll
        for (int n = 0; n < TN; n++) acc[m][n] = 0.f;

    for (int k0 = 0; k0 < K; k0 += BK) {
        // load A tile (transposed into smem)
#pragma unroll
        for (int i = tid * 4; i < BM * BK; i += THREADS * 4) {
            int r = i / BK;
            int kk = i % BK;
            float4 v = make_float4(0.f, 0.f, 0.f, 0.f);
            if (row0 + r < N)
                v = *(const float4*)&A[(size_t)(row0 + r) * K + k0 + kk];
            As[kk + 0][r] = v.x;
            As[kk + 1][r] = v.y;
            As[kk + 2][r] = v.z;
            As[kk + 3][r] = v.w;
        }
        // load B tile
#pragma unroll
        for (int i = tid * 4; i < BK * BN; i += THREADS * 4) {
            int kk = i / BN;
            int c = i % BN;
            *(float4*)&Bs[kk][c] = *(const float4*)&B[(size_t)(k0 + kk) * M + col0 + c];
        }
        __syncthreads();

#pragma unroll
        for (int kk = 0; kk < BK; kk++) {
            float ra[TM], rb[TN];
#pragma unroll
            for (int m = 0; m < TM; m += 4)
                *(float4*)&ra[m] = *(const float4*)&As[kk][ty * TM + m];
#pragma unroll
            for (int n = 0; n < TN; n += 4)
                *(float4*)&rb[n] = *(const float4*)&Bs[kk][tx * TN + n];
#pragma unroll
            for (int m = 0; m < TM; m++)
#pragma unroll
                for (int n = 0; n < TN; n++) acc[m][n] += ra[m] * rb[n];
        }
        __syncthreads();
    }

#pragma unroll
    for (int m = 0; m < TM; m++) {
        int r = row0 + ty * TM + m;
        if (r < N) {
#pragma unroll
            for (int n = 0; n < TN; n += 4) {
                float4 v = make_float4(acc[m][n], acc[m][n + 1], acc[m][n + 2], acc[m][n + 3]);
                *(float4*)&C[(size_t)r * M + col0 + tx * TN + n] = v;
            }
        }
    }
}

// ---------------- attention coefficients: als/ald [N,H] ----------------
template <int H, int C>
__global__ void attn_kernel(const float* __restrict__ h,
                            const float* __restrict__ asr,
                            const float* __restrict__ adr,
                            float* __restrict__ als, float* __restrict__ ald) {
    int idx = blockIdx.x * blockDim.x + threadIdx.x;  // = n*H + head
    if (idx >= NN * H) return;
    int hd = idx % H;
    const float4* hv = (const float4*)(h + (size_t)idx * C);
    const float4* av = (const float4*)(asr + hd * C);
    const float4* dv = (const float4*)(adr + hd * C);
    float s = 0.f, d = 0.f;
#pragma unroll
    for (int i = 0; i < C / 4; i++) {
        float4 x = hv[i], a = av[i], b = dv[i];
        s += x.x * a.x + x.y * a.y + x.z * a.z + x.w * a.w;
        d += x.x * b.x + x.y * b.y + x.z * b.z + x.w * b.w;
    }
    als[idx] = s;
    ald[idx] = d;
}

// ---------------- fused edge pass: w = exp(lrelu(e)), num += w*h[src], den += w ----------------
// softmax max-subtraction skipped: alpha = exp(e)/sum exp(e) is invariant; e is O(1) here.
// NOTE: edge_index is int32 on device (JAX x64 disabled downcasts int64 -> int32).
template <int H, int C>
__global__ void edge_kernel(const int* __restrict__ ei,
                            const float* __restrict__ h,
                            const float* __restrict__ als,
                            const float* __restrict__ ald,
                            float* __restrict__ num, float* __restrict__ den) {
    constexpr int V = H * C / 4;              // float4s per edge
    constexpr int LANES = (V < 32) ? V : 32;  // lanes per edge
    constexpr int EPW = 32 / LANES;           // edges per warp
    constexpr int ITER = V / LANES;

    const long long gtid = (long long)blockIdx.x * blockDim.x + threadIdx.x;
    const int lane = threadIdx.x & 31;
    const long long warp = gtid >> 5;
    const int sub = lane % LANES;
    const long long eidx = warp * EPW + lane / LANES;
    const long long Etot = (long long)NE + NN;
    if (eidx >= Etot) return;

    int s, d;
    if (eidx < NE) {
        s = ei[eidx];
        d = ei[NE + eidx];
    } else {
        s = d = (int)(eidx - NE);
    }

    const float4* hs = (const float4*)(h + (size_t)s * (H * C));
    float4* nd = (float4*)(num + (size_t)d * (H * C));

#pragma unroll
    for (int it = 0; it < ITER; it++) {
        int v = it * LANES + sub;
        int head = (v * 4) / C;
        float e = als[(size_t)s * H + head] + ald[(size_t)d * H + head];
        e = (e > 0.f) ? e : NEG_SLOPE * e;
        float w = __expf(e);
        float4 hv = hs[v];
        if ((v * 4) % C == 0) red_add1(&den[(size_t)d * H + head], w);
        red_add4(&nd[v], make_float4(w * hv.x, w * hv.y, w * hv.z, w * hv.w));
    }
}

// ---------------- finalize: out = num/den + b (+ relu) ----------------
template <int H, int C, bool RELU>
__global__ void fin_kernel(const float* __restrict__ num,
                           const float* __restrict__ den,
                           const float* __restrict__ b, float* __restrict__ out) {
    constexpr int V = H * C / 4;
    int idx = blockIdx.x * blockDim.x + threadIdx.x;
    if (idx >= NN * V) return;
    int n = idx / V;
    int v = idx % V;
    int head = (v * 4) / C;
    float4 nu = ((const float4*)num)[idx];
    float4 bb = ((const float4*)b)[v];
    float inv = 1.f / den[n * H + head];
    float4 o;
    o.x = nu.x * inv + bb.x;
    o.y = nu.y * inv + bb.y;
    o.z = nu.z * inv + bb.z;
    o.w = nu.w * inv + bb.w;
    if (RELU) {
        o.x = fmaxf(o.x, 0.f);
        o.y = fmaxf(o.y, 0.f);
        o.z = fmaxf(o.z, 0.f);
        o.w = fmaxf(o.w, 0.f);
    }
    ((float4*)out)[idx] = o;
}

// ---------------- launch ----------------
static inline int ceil_div_i(long long a, long long b) { return (int)((a + b - 1) / b); }

extern "C" void kernel_launch(void* const* d_in, const int* in_sizes, int n_in,
                              void* d_out, int out_size) {
    const float* x = (const float*)d_in[0];
    const int* ei = (const int*)d_in[1];   // int32 (JAX default x64-disabled)
    const float* W1 = (const float*)d_in[2];
    const float* as1 = (const float*)d_in[3];
    const float* ad1 = (const float*)d_in[4];
    const float* b1 = (const float*)d_in[5];
    const float* W2 = (const float*)d_in[6];
    const float* as2 = (const float*)d_in[7];
    const float* ad2 = (const float*)d_in[8];
    const float* b2 = (const float*)d_in[9];
    const float* W3 = (const float*)d_in[10];
    const float* as3 = (const float*)d_in[11];
    const float* ad3 = (const float*)d_in[12];
    const float* b3 = (const float*)d_in[13];
    const float* W4 = (const float*)d_in[14];
    const float* as4 = (const float*)d_in[15];
    const float* ad4 = (const float*)d_in[16];
    const float* b4 = (const float*)d_in[17];
    float* out = (float*)d_out;

    float *h, *num, *z1, *z2, *r1, *als, *ald, *den;
    cudaGetSymbolAddress((void**)&h, g_h);
    cudaGetSymbolAddress((void**)&num, g_num);
    cudaGetSymbolAddress((void**)&z1, g_z1);
    cudaGetSymbolAddress((void**)&z2, g_z2);
    cudaGetSymbolAddress((void**)&r1, g_r1);
    cudaGetSymbolAddress((void**)&als, g_als);
    cudaGetSymbolAddress((void**)&ald, g_ald);
    cudaGetSymbolAddress((void**)&den, g_den);

    const long long Etot = (long long)NE + NN;
    const int TPB = 256;
    const int rowBlocks = ceil_div_i(NN, 128);

    // ===== Layer 1: 128 -> [8 x 32], relu =====
    cudaMemsetAsync(num, 0, (size_t)NN * 256 * sizeof(float), 0);
    cudaMemsetAsync(den, 0, (size_t)NN * 8 * sizeof(float), 0);
    sgemm_kernel<128, 128, 8, 8, 8><<<dim3(rowBlocks, 2), 256>>>(NN, 128, 256, x, W1, h);
    attn_kernel<8, 32><<<ceil_div_i((long long)NN * 8, TPB), TPB>>>(h, as1, ad1, als, ald);
    edge_kernel<8, 32><<<ceil_div_i(Etot * 32, TPB), TPB>>>(ei, h, als, ald, num, den);
    fin_kernel<8, 32, true><<<ceil_div_i((long long)NN * 64, TPB), TPB>>>(num, den, b1, z1);

    // ===== Layer 2: 256 -> 32 =====
    cudaMemsetAsync(num, 0, (size_t)NN * 32 * sizeof(float), 0);
    cudaMemsetAsync(den, 0, (size_t)NN * 1 * sizeof(float), 0);
    sgemm_kernel<128, 32, 16, 8, 4><<<dim3(rowBlocks, 1), 128>>>(NN, 256, 32, z1, W2, h);
    attn_kernel<1, 32><<<ceil_div_i(NN, TPB), TPB>>>(h, as2, ad2, als, ald);
    // V = 8 float4s per edge -> 8 lanes/edge, 4 edges/warp
    edge_kernel<1, 32><<<ceil_div_i(((Etot + 3) / 4) * 32, TPB), TPB>>>(ei, h, als, ald, num, den);
    fin_kernel<1, 32, false><<<ceil_div_i((long long)NN * 8, TPB), TPB>>>(num, den, b2, z2);

    // ===== Layer 3: 32 -> [8 x 32], relu =====
    cudaMemsetAsync(num, 0, (size_t)NN * 256 * sizeof(float), 0);
    cudaMemsetAsync(den, 0, (size_t)NN * 8 * sizeof(float), 0);
    sgemm_kernel<128, 128, 8, 8, 8><<<dim3(rowBlocks, 2), 256>>>(NN, 32, 256, z2, W3, h);
    attn_kernel<8, 32><<<ceil_div_i((long long)NN * 8, TPB), TPB>>>(h, as3, ad3, als, ald);
    edge_kernel<8, 32><<<ceil_div_i(Etot * 32, TPB), TPB>>>(ei, h, als, ald, num, den);
    fin_kernel<8, 32, true><<<ceil_div_i((long long)NN * 64, TPB), TPB>>>(num, den, b3, r1);

    // ===== Layer 4: 256 -> 128 =====
    cudaMemsetAsync(num, 0, (size_t)NN * 128 * sizeof(float), 0);
    cudaMemsetAsync(den, 0, (size_t)NN * 1 * sizeof(float), 0);
    sgemm_kernel<128, 128, 8, 8, 8><<<dim3(rowBlocks, 1), 256>>>(NN, 256, 128, r1, W4, h);
    attn_kernel<1, 128><<<ceil_div_i(NN, TPB), TPB>>>(h, as4, ad4, als, ald);
    edge_kernel<1, 128><<<ceil_div_i(Etot * 32, TPB), TPB>>>(ei, h, als, ald, num, den);
    fin_kernel<1, 128, false><<<ceil_div_i((long long)NN * 32, TPB), TPB>>>(num, den, b4, out);
}

// round 5
// speedup vs baseline: 1.5404x; 1.5404x over previous
#include <cuda_runtime.h>
#include <cstdint>

#define NN 50000
#define NE 800000
constexpr float NEG_SLOPE = 0.2f;

// ---------------- scratch (device globals; no allocation) ----------------
__device__ float g_h  [NN * 256];
__device__ float g_z1 [NN * 256];
__device__ float g_z2 [NN * 32];
__device__ float g_r1 [NN * 256];
__device__ float g_als[NN * 8];
__device__ float g_ald[NN * 8];
__device__ int   g_deg[NN];
__device__ int   g_cnt[NN];
__device__ int   g_off[NN + 1];
__device__ int   g_csr[NE + NN];

// ================= CSR build =================
__global__ void hist_kernel(const int* __restrict__ ei, int* __restrict__ deg) {
    int e = blockIdx.x * blockDim.x + threadIdx.x;
    if (e < NE) atomicAdd(&deg[ei[NE + e]], 1);
}

// single-block scan: off[i+1] = sum_{j<=i} (deg[j]+1), off[0]=0
__global__ void scan_kernel(const int* __restrict__ deg, int* __restrict__ off) {
    __shared__ int wsum[32];
    __shared__ int carry_s;
    int tid = threadIdx.x, lane = tid & 31, wid = tid >> 5;
    if (tid == 0) { carry_s = 0; off[0] = 0; }
    __syncthreads();
    for (int base = 0; base < NN; base += 1024) {
        int i = base + tid;
        int v = (i < NN) ? deg[i] + 1 : 0;
        int x = v;
#pragma unroll
        for (int o = 1; o < 32; o <<= 1) {
            int t = __shfl_up_sync(0xffffffffu, x, o);
            if (lane >= o) x += t;
        }
        if (lane == 31) wsum[wid] = x;
        __syncthreads();
        if (wid == 0) {
            int y = wsum[lane];
#pragma unroll
            for (int o = 1; o < 32; o <<= 1) {
                int t = __shfl_up_sync(0xffffffffu, y, o);
                if (lane >= o) y += t;
            }
            wsum[lane] = y;
        }
        __syncthreads();
        int incl = x + (wid > 0 ? wsum[wid - 1] : 0) + carry_s;
        if (i < NN) off[i + 1] = incl;
        __syncthreads();
        if (tid == 1023) carry_s = incl;
        __syncthreads();
    }
}

__global__ void scatter_kernel(const int* __restrict__ ei, const int* __restrict__ off,
                               int* __restrict__ cnt, int* __restrict__ csr) {
    int e = blockIdx.x * blockDim.x + threadIdx.x;
    if (e < NE) {
        int d = ei[NE + e];
        int pos = off[d] + atomicAdd(&cnt[d], 1);
        csr[pos] = ei[e];
    } else if (e < NE + NN) {
        int n = e - NE;
        csr[off[n + 1] - 1] = n;  // self loop in last slot
    }
}

// ================= SGEMM: C[N,M] = A[N,K] @ B[K,M] =================
template <int BM, int BN, int BK, int TM, int TN>
__global__ void __launch_bounds__((BM / TM) * (BN / TN))
sgemm_kernel(int N, int K, int M,
             const float* __restrict__ A, const float* __restrict__ B,
             float* __restrict__ C) {
    constexpr int TX = BN / TN;
    constexpr int TY = BM / TM;
    constexpr int THREADS = TX * TY;

    __shared__ float As[BK][BM];
    __shared__ float Bs[BK][BN];

    const int tid = threadIdx.x;
    const int tx = tid % TX;
    const int ty = tid / TX;
    const int row0 = blockIdx.x * BM;
    const int col0 = blockIdx.y * BN;

    float acc[TM][TN];
#pragma unroll
    for (int m = 0; m < TM; m++)
#pragma unroll
        for (int n = 0; n < TN; n++) acc[m][n] = 0.f;

    for (int k0 = 0; k0 < K; k0 += BK) {
#pragma unroll
        for (int i = tid * 4; i < BM * BK; i += THREADS * 4) {
            int r = i / BK;
            int kk = i % BK;
            float4 v = make_float4(0.f, 0.f, 0.f, 0.f);
            if (row0 + r < N)
                v = *(const float4*)&A[(size_t)(row0 + r) * K + k0 + kk];
            As[kk + 0][r] = v.x;
            As[kk + 1][r] = v.y;
            As[kk + 2][r] = v.z;
            As[kk + 3][r] = v.w;
        }
#pragma unroll
        for (int i = tid * 4; i < BK * BN; i += THREADS * 4) {
            int kk = i / BN;
            int c = i % BN;
            *(float4*)&Bs[kk][c] = *(const float4*)&B[(size_t)(k0 + kk) * M + col0 + c];
        }
        __syncthreads();

#pragma unroll
        for (int kk = 0; kk < BK; kk++) {
            float ra[TM], rb[TN];
#pragma unroll
            for (int m = 0; m < TM; m += 4)
                *(float4*)&ra[m] = *(const float4*)&As[kk][ty * TM + m];
#pragma unroll
            for (int n = 0; n < TN; n += 4)
                *(float4*)&rb[n] = *(const float4*)&Bs[kk][tx * TN + n];
#pragma unroll
            for (int m = 0; m < TM; m++)
#pragma unroll
                for (int n = 0; n < TN; n++) acc[m][n] += ra[m] * rb[n];
        }
        __syncthreads();
    }

#pragma unroll
    for (int m = 0; m < TM; m++) {
        int r = row0 + ty * TM + m;
        if (r < N) {
#pragma unroll
            for (int n = 0; n < TN; n += 4) {
                float4 v = make_float4(acc[m][n], acc[m][n + 1], acc[m][n + 2], acc[m][n + 3]);
                *(float4*)&C[(size_t)r * M + col0 + tx * TN + n] = v;
            }
        }
    }
}

// ================= attention coefficients: als/ald [N,H] =================
template <int H, int C>
__global__ void attn_kernel(const float* __restrict__ h,
                            const float* __restrict__ asr,
                            const float* __restrict__ adr,
                            float* __restrict__ als, float* __restrict__ ald) {
    int idx = blockIdx.x * blockDim.x + threadIdx.x;  // = n*H + head
    if (idx >= NN * H) return;
    int hd = idx % H;
    const float4* hv = (const float4*)(h + (size_t)idx * C);
    const float4* av = (const float4*)(asr + hd * C);
    const float4* dv = (const float4*)(adr + hd * C);
    float s = 0.f, d = 0.f;
#pragma unroll
    for (int i = 0; i < C / 4; i++) {
        float4 x = hv[i], a = av[i], b = dv[i];
        s += x.x * a.x + x.y * a.y + x.z * a.z + x.w * a.w;
        d += x.x * b.x + x.y * b.y + x.z * b.z + x.w * b.w;
    }
    als[idx] = s;
    ald[idx] = d;
}

// ================= CSR aggregation (softmax-normalized), fused bias/relu =======
// H=8, C=32: one warp per node; lane owns float4 columns lane and lane+32.
template <bool RELU>
__global__ void __launch_bounds__(256)
agg8_kernel(const int* __restrict__ off, const int* __restrict__ csr,
            const float* __restrict__ h, const float* __restrict__ als,
            const float* __restrict__ ald, const float* __restrict__ b,
            float* __restrict__ out) {
    int node = blockIdx.x * 8 + (threadIdx.x >> 5);
    if (node >= NN) return;
    int lane = threadIdx.x & 31;
    int hl = lane >> 3, hh = hl + 4;
    float aldl = ald[node * 8 + hl], aldh = ald[node * 8 + hh];
    float4 accl = make_float4(0, 0, 0, 0), acch = make_float4(0, 0, 0, 0);
    float wsl = 0.f, wsh = 0.f;
    int s0 = off[node], s1 = off[node + 1];
    for (int i = s0; i < s1; i++) {
        int src = __ldg(&csr[i]);
        const float4* hs = (const float4*)(h + (size_t)src * 256);
        float el = __ldg(&als[src * 8 + hl]) + aldl;
        float eh = __ldg(&als[src * 8 + hh]) + aldh;
        el = el > 0.f ? el : NEG_SLOPE * el;
        eh = eh > 0.f ? eh : NEG_SLOPE * eh;
        float wl = __expf(el), wh = __expf(eh);
        float4 h1 = hs[lane], h2 = hs[lane + 32];
        accl.x += wl * h1.x; accl.y += wl * h1.y; accl.z += wl * h1.z; accl.w += wl * h1.w;
        acch.x += wh * h2.x; acch.y += wh * h2.y; acch.z += wh * h2.z; acch.w += wh * h2.w;
        wsl += wl; wsh += wh;
    }
    float invl = 1.f / wsl, invh = 1.f / wsh;
    float4 b1 = ((const float4*)b)[lane], b2 = ((const float4*)b)[lane + 32];
    float4 o1 = make_float4(accl.x * invl + b1.x, accl.y * invl + b1.y,
                            accl.z * invl + b1.z, accl.w * invl + b1.w);
    float4 o2 = make_float4(acch.x * invh + b2.x, acch.y * invh + b2.y,
                            acch.z * invh + b2.z, acch.w * invh + b2.w);
    if (RELU) {
        o1.x = fmaxf(o1.x, 0.f); o1.y = fmaxf(o1.y, 0.f);
        o1.z = fmaxf(o1.z, 0.f); o1.w = fmaxf(o1.w, 0.f);
        o2.x = fmaxf(o2.x, 0.f); o2.y = fmaxf(o2.y, 0.f);
        o2.z = fmaxf(o2.z, 0.f); o2.w = fmaxf(o2.w, 0.f);
    }
    float4* op = (float4*)(out + (size_t)node * 256);
    op[lane] = o1;
    op[lane + 32] = o2;
}

// H=1, C=32: warp per node, 4 edges/iter (8 lanes per edge), butterfly combine.
__global__ void __launch_bounds__(256)
agg1c32_kernel(const int* __restrict__ off, const int* __restrict__ csr,
               const float* __restrict__ h, const float* __restrict__ als,
               const float* __restrict__ ald, const float* __restrict__ b,
               float* __restrict__ out) {
    int node = blockIdx.x * 8 + (threadIdx.x >> 5);
    if (node >= NN) return;
    int lane = threadIdx.x & 31, sub = lane >> 3, col = lane & 7;
    float aldn = ald[node];
    float4 acc = make_float4(0, 0, 0, 0);
    float ws = 0.f;
    int s0 = off[node], s1 = off[node + 1];
    for (int i = s0 + sub; i < s1; i += 4) {
        int src = __ldg(&csr[i]);
        float e = __ldg(&als[src]) + aldn;
        e = e > 0.f ? e : NEG_SLOPE * e;
        float w = __expf(e);
        float4 hv = ((const float4*)(h + (size_t)src * 32))[col];
        acc.x += w * hv.x; acc.y += w * hv.y; acc.z += w * hv.z; acc.w += w * hv.w;
        ws += w;
    }
#pragma unroll
    for (int m = 8; m <= 16; m <<= 1) {
        acc.x += __shfl_xor_sync(0xffffffffu, acc.x, m);
        acc.y += __shfl_xor_sync(0xffffffffu, acc.y, m);
        acc.z += __shfl_xor_sync(0xffffffffu, acc.z, m);
        acc.w += __shfl_xor_sync(0xffffffffu, acc.w, m);
        ws    += __shfl_xor_sync(0xffffffffu, ws, m);
    }
    if (sub == 0) {
        float inv = 1.f / ws;
        float4 bb = ((const float4*)b)[col];
        float4 o = make_float4(acc.x * inv + bb.x, acc.y * inv + bb.y,
                               acc.z * inv + bb.z, acc.w * inv + bb.w);
        ((float4*)(out + (size_t)node * 32))[col] = o;
    }
}

// H=1, C=128: warp per node, lane owns one float4 column.
__global__ void __launch_bounds__(256)
agg1c128_kernel(const int* __restrict__ off, const int* __restrict__ csr,
                const float* __restrict__ h, const float* __restrict__ als,
                const float* __restrict__ ald, const float* __restrict__ b,
                float* __restrict__ out) {
    int node = blockIdx.x * 8 + (threadIdx.x >> 5);
    if (node >= NN) return;
    int lane = threadIdx.x & 31;
    float aldn = ald[node];
    float4 acc = make_float4(0, 0, 0, 0);
    float ws = 0.f;
    int s0 = off[node], s1 = off[node + 1];
    for (int i = s0; i < s1; i++) {
        int src = __ldg(&csr[i]);
        float e = __ldg(&als[src]) + aldn;
        e = e > 0.f ? e : NEG_SLOPE * e;
        float w = __expf(e);
        float4 hv = ((const float4*)(h + (size_t)src * 128))[lane];
        acc.x += w * hv.x; acc.y += w * hv.y; acc.z += w * hv.z; acc.w += w * hv.w;
        ws += w;
    }
    float inv = 1.f / ws;
    float4 bb = ((const float4*)b)[lane];
    float4 o = make_float4(acc.x * inv + bb.x, acc.y * inv + bb.y,
                           acc.z * inv + bb.z, acc.w * inv + bb.w);
    ((float4*)(out + (size_t)node * 128))[lane] = o;
}

// ================= launch =================
static inline int ceil_div_i(long long a, long long b) { return (int)((a + b - 1) / b); }

extern "C" void kernel_launch(void* const* d_in, const int* in_sizes, int n_in,
                              void* d_out, int out_size) {
    const float* x = (const float*)d_in[0];
    const int* ei = (const int*)d_in[1];   // int32 (JAX x64 disabled)
    const float* W1 = (const float*)d_in[2];
    const float* as1 = (const float*)d_in[3];
    const float* ad1 = (const float*)d_in[4];
    const float* b1 = (const float*)d_in[5];
    const float* W2 = (const float*)d_in[6];
    const float* as2 = (const float*)d_in[7];
    const float* ad2 = (const float*)d_in[8];
    const float* b2 = (const float*)d_in[9];
    const float* W3 = (const float*)d_in[10];
    const float* as3 = (const float*)d_in[11];
    const float* ad3 = (const float*)d_in[12];
    const float* b3 = (const float*)d_in[13];
    const float* W4 = (const float*)d_in[14];
    const float* as4 = (const float*)d_in[15];
    const float* ad4 = (const float*)d_in[16];
    const float* b4 = (const float*)d_in[17];
    float* out = (float*)d_out;

    float *h, *z1, *z2, *r1, *als, *ald;
    int *deg, *cnt, *off, *csr;
    cudaGetSymbolAddress((void**)&h, g_h);
    cudaGetSymbolAddress((void**)&z1, g_z1);
    cudaGetSymbolAddress((void**)&z2, g_z2);
    cudaGetSymbolAddress((void**)&r1, g_r1);
    cudaGetSymbolAddress((void**)&als, g_als);
    cudaGetSymbolAddress((void**)&ald, g_ald);
    cudaGetSymbolAddress((void**)&deg, g_deg);
    cudaGetSymbolAddress((void**)&cnt, g_cnt);
    cudaGetSymbolAddress((void**)&off, g_off);
    cudaGetSymbolAddress((void**)&csr, g_csr);

    const int TPB = 256;
    const int rowBlocks = ceil_div_i(NN, 128);
    const int aggBlocks = ceil_div_i(NN, 8);

    // ---- CSR build (by dst), reused by all 4 layers ----
    cudaMemsetAsync(deg, 0, NN * sizeof(int), 0);
    cudaMemsetAsync(cnt, 0, NN * sizeof(int), 0);
    hist_kernel<<<ceil_div_i(NE, TPB), TPB>>>(ei, deg);
    scan_kernel<<<1, 1024>>>(deg, off);
    scatter_kernel<<<ceil_div_i(NE + NN, TPB), TPB>>>(ei, off, cnt, csr);

    // ===== Layer 1: 128 -> [8 x 32], relu =====
    sgemm_kernel<128, 128, 8, 8, 8><<<dim3(rowBlocks, 2), 256>>>(NN, 128, 256, x, W1, h);
    attn_kernel<8, 32><<<ceil_div_i((long long)NN * 8, TPB), TPB>>>(h, as1, ad1, als, ald);
    agg8_kernel<true><<<aggBlocks, TPB>>>(off, csr, h, als, ald, b1, z1);

    // ===== Layer 2: 256 -> 32 =====
    sgemm_kernel<128, 32, 16, 8, 4><<<dim3(rowBlocks, 1), 128>>>(NN, 256, 32, z1, W2, h);
    attn_kernel<1, 32><<<ceil_div_i(NN, TPB), TPB>>>(h, as2, ad2, als, ald);
    agg1c32_kernel<<<aggBlocks, TPB>>>(off, csr, h, als, ald, b2, z2);

    // ===== Layer 3: 32 -> [8 x 32], relu =====
    sgemm_kernel<128, 128, 8, 8, 8><<<dim3(rowBlocks, 2), 256>>>(NN, 32, 256, z2, W3, h);
    attn_kernel<8, 32><<<ceil_div_i((long long)NN * 8, TPB), TPB>>>(h, as3, ad3, als, ald);
    agg8_kernel<true><<<aggBlocks, TPB>>>(off, csr, h, als, ald, b3, r1);

    // ===== Layer 4: 256 -> 128 =====
    sgemm_kernel<128, 128, 8, 8, 8><<<dim3(rowBlocks, 1), 256>>>(NN, 256, 128, r1, W4, h);
    attn_kernel<1, 128><<<ceil_div_i(NN, TPB), TPB>>>(h, as4, ad4, als, ald);
    agg1c128_kernel<<<aggBlocks, TPB>>>(off, csr, h, als, ald, b4, out);
}